// round 3
// baseline (speedup 1.0000x reference)
#include <cuda_runtime.h>
#include <math.h>

// Problem constants
#define S     64
#define SS    (S*S)          // 4096
#define SSS   (S*S*S)        // 262144
#define C_IN  16
#define C_HID 64
#define NELEM (C_IN*SSS)     // 4194304
#define NSTEPS 20
#define DT_F   0.05f

// Tiling
#define T1X 16
#define T1Y 4
#define T1Z 4
#define ICC 8                       // input-channel chunk
#define SIN_N (ICC*6*6*18)          // 5184 floats, input tile w/ halo
#define SW1_N (ICC*27*C_HID)        // 13824 floats
#define SW2_N (ICC*27*C_IN)         // 3456 floats

// Scratch (device globals: allocation-free rule)
__device__ float g_y[NELEM];
__device__ float g_h[C_HID*SSS];
__device__ float g_w1r[C_IN*27*C_HID];   // [ic][tap][oc]
__device__ float g_w2r[C_HID*27*C_IN];   // [ic][tap][oc]

// ---------------------------------------------------------------------------
// Reorder weights: w[oc][ic][tap] -> wr[ic][tap][oc]  (both are 27648 elems)
// ---------------------------------------------------------------------------
__global__ void reorder_w_kernel(const float* __restrict__ w1,
                                 const float* __restrict__ w2) {
    int i = blockIdx.x * blockDim.x + threadIdx.x;
    if (i >= C_IN*27*C_HID) return;
    {
        int oc = i & 63; int t = i >> 6; int tap = t % 27; int ic = t / 27;
        g_w1r[i] = w1[(oc*C_IN + ic)*27 + tap];
    }
    {
        int oc = i & 15; int t = i >> 4; int tap = t % 27; int ic = t / 27;
        g_w2r[i] = w2[(oc*C_HID + ic)*27 + tap];
    }
}

// ---------------------------------------------------------------------------
// Conv1 (16 -> 64) + tanh.  Tile 16x4x4 voxels. 256 threads:
//   og = tid&3  -> 16 output channels (og*16 .. og*16+15)
//   vg = tid>>2 -> 4 consecutive x-voxels (xg), y (yy), z (zz)
// acc[v*16+o], v in 0..3 voxels, o in 0..15 channels -> 64 regs of ILP.
// ---------------------------------------------------------------------------
__global__ __launch_bounds__(256, 2)
void conv1_tanh_kernel(const float* __restrict__ yin,
                       float* __restrict__ hout,
                       const float* __restrict__ b1) {
    extern __shared__ float sm[];
    float* s_in = sm;              // [ICC][6][6][18]
    float* s_w  = sm + SIN_N;      // [ICC][27][64]

    const int tid = threadIdx.x;
    const int og  = tid & 3;
    const int vg  = tid >> 2;
    const int xg  = vg & 3;
    const int yy  = (vg >> 2) & 3;
    const int zz  = vg >> 4;
    const int x0  = blockIdx.x * T1X;
    const int y0  = blockIdx.y * T1Y;
    const int z0  = blockIdx.z * T1Z;

    float acc[64];
    #pragma unroll
    for (int i = 0; i < 64; i++) acc[i] = 0.f;

    for (int c = 0; c < C_IN/ICC; c++) {
        const int ic0 = c * ICC;
        // cooperative input tile load (with zero halo)
        for (int i = tid; i < SIN_N; i += 256) {
            int xi = i % 18; int r = i / 18;
            int yi = r % 6;  r /= 6;
            int zi = r % 6;  int ici = r / 6;
            int gx = x0 + xi - 1, gy = y0 + yi - 1, gz = z0 + zi - 1;
            float v = 0.f;
            if ((unsigned)gx < S && (unsigned)gy < S && (unsigned)gz < S)
                v = yin[(ic0 + ici)*SSS + gz*SS + gy*S + gx];
            s_in[i] = v;
        }
        // weight chunk (contiguous slice)
        for (int i = tid; i < SW1_N; i += 256)
            s_w[i] = g_w1r[ic0*27*C_HID + i];
        __syncthreads();

        #pragma unroll 1
        for (int ici = 0; ici < ICC; ici++) {
            #pragma unroll 1
            for (int dz = 0; dz < 3; dz++) {
                #pragma unroll
                for (int dy = 0; dy < 3; dy++) {
                    const float* base =
                        &s_in[((ici*6 + zz + dz)*6 + yy + dy)*18 + xg*4];
                    float rr[6];
                    #pragma unroll
                    for (int k = 0; k < 6; k++) rr[k] = base[k];
                    #pragma unroll
                    for (int dx = 0; dx < 3; dx++) {
                        const float4* wp = (const float4*)
                            &s_w[(ici*27 + (dz*3 + dy)*3 + dx)*C_HID + og*16];
                        float4 w0 = wp[0], w1v = wp[1], w2v = wp[2], w3v = wp[3];
                        float wv[16] = {w0.x,w0.y,w0.z,w0.w,
                                        w1v.x,w1v.y,w1v.z,w1v.w,
                                        w2v.x,w2v.y,w2v.z,w2v.w,
                                        w3v.x,w3v.y,w3v.z,w3v.w};
                        #pragma unroll
                        for (int v = 0; v < 4; v++) {
                            float in = rr[dx + v];
                            #pragma unroll
                            for (int o = 0; o < 16; o++)
                                acc[v*16 + o] += in * wv[o];
                        }
                    }
                }
            }
        }
        __syncthreads();
    }

    // bias + tanh + vectorized store
    const int ox = x0 + xg*4, oy = y0 + yy, oz = z0 + zz;
    #pragma unroll
    for (int o = 0; o < 16; o++) {
        int oc = og*16 + o;
        float b = b1[oc];
        float4 f;
        f.x = tanhf(acc[0*16 + o] + b);
        f.y = tanhf(acc[1*16 + o] + b);
        f.z = tanhf(acc[2*16 + o] + b);
        f.w = tanhf(acc[3*16 + o] + b);
        *(float4*)&hout[oc*SSS + oz*SS + oy*S + ox] = f;
    }
}

// ---------------------------------------------------------------------------
// Conv2 (64 -> 16) + Euler update: y += (conv(h)+b2)*dt + sigma*sqrt(dt)*z
//   og = tid&3 -> 4 output channels (og*4 .. og*4+3); vg like conv1.
// ---------------------------------------------------------------------------
__global__ __launch_bounds__(256, 2)
void conv2_update_kernel(const float* __restrict__ hin,
                         float* __restrict__ yio,
                         const float* __restrict__ b2,
                         const float* __restrict__ nz) {
    __shared__ float s_in[SIN_N];   // [ICC][6][6][18]
    __shared__ float s_w[SW2_N];    // [ICC][27][16]

    const int tid = threadIdx.x;
    const int og  = tid & 3;
    const int vg  = tid >> 2;
    const int xg  = vg & 3;
    const int yy  = (vg >> 2) & 3;
    const int zz  = vg >> 4;
    const int x0  = blockIdx.x * T1X;
    const int y0  = blockIdx.y * T1Y;
    const int z0  = blockIdx.z * T1Z;

    float acc[16];
    #pragma unroll
    for (int i = 0; i < 16; i++) acc[i] = 0.f;

    for (int c = 0; c < C_HID/ICC; c++) {
        const int ic0 = c * ICC;
        for (int i = tid; i < SIN_N; i += 256) {
            int xi = i % 18; int r = i / 18;
            int yi = r % 6;  r /= 6;
            int zi = r % 6;  int ici = r / 6;
            int gx = x0 + xi - 1, gy = y0 + yi - 1, gz = z0 + zi - 1;
            float v = 0.f;
            if ((unsigned)gx < S && (unsigned)gy < S && (unsigned)gz < S)
                v = hin[(ic0 + ici)*SSS + gz*SS + gy*S + gx];
            s_in[i] = v;
        }
        for (int i = tid; i < SW2_N; i += 256)
            s_w[i] = g_w2r[ic0*27*C_IN + i];
        __syncthreads();

        #pragma unroll 1
        for (int ici = 0; ici < ICC; ici++) {
            #pragma unroll 1
            for (int dz = 0; dz < 3; dz++) {
                #pragma unroll
                for (int dy = 0; dy < 3; dy++) {
                    const float* base =
                        &s_in[((ici*6 + zz + dz)*6 + yy + dy)*18 + xg*4];
                    float rr[6];
                    #pragma unroll
                    for (int k = 0; k < 6; k++) rr[k] = base[k];
                    #pragma unroll
                    for (int dx = 0; dx < 3; dx++) {
                        float4 w = *(const float4*)
                            &s_w[(ici*27 + (dz*3 + dy)*3 + dx)*C_IN + og*4];
                        float wv[4] = {w.x, w.y, w.z, w.w};
                        #pragma unroll
                        for (int v = 0; v < 4; v++) {
                            float in = rr[dx + v];
                            #pragma unroll
                            for (int o = 0; o < 4; o++)
                                acc[v*4 + o] += in * wv[o];
                        }
                    }
                }
            }
        }
        __syncthreads();
    }

    // Euler-Maruyama update (in-place on y; pointwise -> safe)
    const float sn = 0.1f * 0.22360679774997896f;   // sigma * sqrt(dt)
    const int ox = x0 + xg*4, oy = y0 + yy, oz = z0 + zz;
    #pragma unroll
    for (int o = 0; o < 4; o++) {
        int oc  = og*4 + o;
        float b = b2[oc];
        int idx = oc*SSS + oz*SS + oy*S + ox;
        float4 yv = *(const float4*)&yio[idx];
        float4 zv = *(const float4*)&nz[idx];
        float4 ov;
        ov.x = yv.x + (acc[0*4 + o] + b)*DT_F + sn*zv.x;
        ov.y = yv.y + (acc[1*4 + o] + b)*DT_F + sn*zv.y;
        ov.z = yv.z + (acc[2*4 + o] + b)*DT_F + sn*zv.z;
        ov.w = yv.w + (acc[3*4 + o] + b)*DT_F + sn*zv.w;
        *(float4*)&yio[idx] = ov;
    }
}

// ---------------------------------------------------------------------------
// Launch: inputs = [x, integration_time, w1, b1, w2, b2, noise]
// ---------------------------------------------------------------------------
extern "C" void kernel_launch(void* const* d_in, const int* in_sizes, int n_in,
                              void* d_out, int out_size) {
    const float* x  = (const float*)d_in[0];
    const float* w1 = (const float*)d_in[2];
    const float* b1 = (const float*)d_in[3];
    const float* w2 = (const float*)d_in[4];
    const float* b2 = (const float*)d_in[5];
    const float* nz = (const float*)d_in[6];

    float *yp, *hp;
    cudaGetSymbolAddress((void**)&yp, g_y);
    cudaGetSymbolAddress((void**)&hp, g_h);

    cudaFuncSetAttribute(conv1_tanh_kernel,
                         cudaFuncAttributeMaxDynamicSharedMemorySize,
                         (SIN_N + SW1_N) * (int)sizeof(float));

    cudaMemcpyAsync(yp, x, (size_t)NELEM * sizeof(float),
                    cudaMemcpyDeviceToDevice, 0);

    reorder_w_kernel<<<(C_IN*27*C_HID + 255)/256, 256>>>(w1, w2);

    dim3 grid(S/T1X, S/T1Y, S/T1Z);   // (4,16,16) = 1024 blocks
    for (int s = 0; s < NSTEPS; s++) {
        conv1_tanh_kernel<<<grid, 256, (SIN_N + SW1_N)*(int)sizeof(float)>>>(
            yp, hp, b1);
        conv2_update_kernel<<<grid, 256>>>(hp, yp, b2,
                                           nz + (size_t)s * NELEM);
    }

    cudaMemcpyAsync(d_out, yp, (size_t)NELEM * sizeof(float),
                    cudaMemcpyDeviceToDevice, 0);
}

// round 4
// speedup vs baseline: 1.1934x; 1.1934x over previous
#include <cuda_runtime.h>
#include <math.h>

// Problem constants
#define S     64
#define SS    (S*S)          // 4096
#define SSS   (S*S*S)        // 262144
#define C_IN  16
#define C_HID 64
#define NELEM (C_IN*SSS)     // 4194304
#define NSTEPS 20
#define DT_F   0.05f

#define ICC   8              // input-channel chunk
#define XPAD  20             // padded x-row (80B, 16B-aligned)

// conv1: tile 16x4x4
#define SIN1_N (ICC*6*6*XPAD)     // 5760 floats
#define SW1_N  (ICC*27*C_HID)     // 13824 floats
// conv2: tile 16x8x8
#define SIN2_N (ICC*10*10*XPAD)   // 16000 floats
#define SW2_N  (ICC*27*C_IN)      // 3456 floats

// Scratch (device globals: allocation-free rule)
__device__ float g_y[NELEM];
__device__ float g_h[C_HID*SSS];
__device__ float g_w1r[C_IN*27*C_HID];   // [ic][tap][oc]
__device__ float g_w2r[C_HID*27*C_IN];   // [ic][tap][oc]

// ---------------------------------------------------------------------------
// Reorder weights: w[oc][ic][tap] -> wr[ic][tap][oc]
// ---------------------------------------------------------------------------
__global__ void reorder_w_kernel(const float* __restrict__ w1,
                                 const float* __restrict__ w2) {
    int i = blockIdx.x * blockDim.x + threadIdx.x;
    if (i >= C_IN*27*C_HID) return;
    {
        int oc = i & 63; int t = i >> 6; int tap = t % 27; int ic = t / 27;
        g_w1r[i] = w1[(oc*C_IN + ic)*27 + tap];
    }
    {
        int oc = i & 15; int t = i >> 4; int tap = t % 27; int ic = t / 27;
        g_w2r[i] = w2[(oc*C_HID + ic)*27 + tap];
    }
}

// ---------------------------------------------------------------------------
// Conv1 (16 -> 64) + tanh.  Tile 16x4x4.  256 threads:
//   og = tid&7  -> 8 output channels (og*8 .. og*8+7)
//   vg = tid>>3 -> 8 consecutive x-voxels; xg in {0,1}, yy 0..3, zz 0..3
// acc[v*8+o]: 64 regs.  Shared fl/FMA = 0.177 (was 0.281).
// ---------------------------------------------------------------------------
__global__ __launch_bounds__(256, 2)
void conv1_tanh_kernel(const float* __restrict__ yin,
                       float* __restrict__ hout,
                       const float* __restrict__ b1) {
    extern __shared__ float sm[];
    float* s_in = sm;               // [ICC][6][6][XPAD]
    float* s_w  = sm + SIN1_N;      // [ICC][27][64]

    const int tid = threadIdx.x;
    const int og  = tid & 7;
    const int vg  = tid >> 3;
    const int xg  = vg & 1;
    const int yy  = (vg >> 1) & 3;
    const int zz  = vg >> 3;
    const int x0  = blockIdx.x * 16;
    const int y0  = blockIdx.y * 4;
    const int z0  = blockIdx.z * 4;

    float acc[64];
    #pragma unroll
    for (int i = 0; i < 64; i++) acc[i] = 0.f;

    for (int c = 0; c < C_IN/ICC; c++) {
        const int ic0 = c * ICC;
        // cooperative input tile load (zero halo), padded rows
        for (int i = tid; i < ICC*6*6*18; i += 256) {
            int xi = i % 18; int r = i / 18;
            int yi = r % 6;  r /= 6;
            int zi = r % 6;  int ici = r / 6;
            int gx = x0 + xi - 1, gy = y0 + yi - 1, gz = z0 + zi - 1;
            float v = 0.f;
            if ((unsigned)gx < S && (unsigned)gy < S && (unsigned)gz < S)
                v = yin[(ic0 + ici)*SSS + gz*SS + gy*S + gx];
            s_in[((ici*6 + zi)*6 + yi)*XPAD + xi] = v;
        }
        for (int i = tid; i < SW1_N; i += 256)
            s_w[i] = g_w1r[ic0*27*C_HID + i];
        __syncthreads();

        #pragma unroll 1
        for (int ici = 0; ici < ICC; ici++) {
            #pragma unroll 1
            for (int dz = 0; dz < 3; dz++) {
                #pragma unroll
                for (int dy = 0; dy < 3; dy++) {
                    const float* base =
                        &s_in[((ici*6 + zz + dz)*6 + yy + dy)*XPAD + xg*8];
                    float4 ra = *(const float4*)(base);
                    float4 rb = *(const float4*)(base + 4);
                    float2 rc = *(const float2*)(base + 8);
                    float rr[10] = {ra.x,ra.y,ra.z,ra.w,
                                    rb.x,rb.y,rb.z,rb.w, rc.x,rc.y};
                    #pragma unroll
                    for (int dx = 0; dx < 3; dx++) {
                        const float4* wp = (const float4*)
                            &s_w[((ici*27 + (dz*3 + dy)*3 + dx) << 6) + og*8];
                        float4 w0 = wp[0], w1v = wp[1];
                        float wv[8] = {w0.x,w0.y,w0.z,w0.w,
                                       w1v.x,w1v.y,w1v.z,w1v.w};
                        #pragma unroll
                        for (int v = 0; v < 8; v++) {
                            float in = rr[dx + v];
                            #pragma unroll
                            for (int o = 0; o < 8; o++)
                                acc[v*8 + o] += in * wv[o];
                        }
                    }
                }
            }
        }
        __syncthreads();
    }

    // bias + tanh + vectorized store (8 oc x 8 voxels)
    const int ox = x0 + xg*8, oy = y0 + yy, oz = z0 + zz;
    #pragma unroll
    for (int o = 0; o < 8; o++) {
        int oc = og*8 + o;
        float b = b1[oc];
        float4 f0, f1;
        f0.x = tanhf(acc[0*8+o] + b); f0.y = tanhf(acc[1*8+o] + b);
        f0.z = tanhf(acc[2*8+o] + b); f0.w = tanhf(acc[3*8+o] + b);
        f1.x = tanhf(acc[4*8+o] + b); f1.y = tanhf(acc[5*8+o] + b);
        f1.z = tanhf(acc[6*8+o] + b); f1.w = tanhf(acc[7*8+o] + b);
        float* p = &hout[oc*SSS + oz*SS + oy*S + ox];
        *(float4*)p       = f0;
        *(float4*)(p + 4) = f1;
    }
}

// ---------------------------------------------------------------------------
// Conv2 (64 -> 16) + Euler update.  Tile 16x8x8 (1024 voxels).  256 threads:
//   og = tid&1  -> 8 output channels (og*8 .. og*8+7)
//   vg = tid>>1 -> 8 x-voxels; xg in {0,1}, yy 0..7, zz 0..7
// Shared fl/FMA = 0.177 (was 0.375).
// ---------------------------------------------------------------------------
__global__ __launch_bounds__(256, 2)
void conv2_update_kernel(const float* __restrict__ hin,
                         float* __restrict__ yio,
                         const float* __restrict__ b2,
                         const float* __restrict__ nz) {
    extern __shared__ float sm[];
    float* s_in = sm;               // [ICC][10][10][XPAD]
    float* s_w  = sm + SIN2_N;      // [ICC][27][16]

    const int tid = threadIdx.x;
    const int og  = tid & 1;
    const int vg  = tid >> 1;
    const int xg  = vg & 1;
    const int yy  = (vg >> 1) & 7;
    const int zz  = vg >> 4;
    const int x0  = blockIdx.x * 16;
    const int y0  = blockIdx.y * 8;
    const int z0  = blockIdx.z * 8;

    float acc[64];
    #pragma unroll
    for (int i = 0; i < 64; i++) acc[i] = 0.f;

    for (int c = 0; c < C_HID/ICC; c++) {
        const int ic0 = c * ICC;
        for (int i = tid; i < ICC*10*10*18; i += 256) {
            int xi = i % 18; int r = i / 18;
            int yi = r % 10; r /= 10;
            int zi = r % 10; int ici = r / 10;
            int gx = x0 + xi - 1, gy = y0 + yi - 1, gz = z0 + zi - 1;
            float v = 0.f;
            if ((unsigned)gx < S && (unsigned)gy < S && (unsigned)gz < S)
                v = hin[(ic0 + ici)*SSS + gz*SS + gy*S + gx];
            s_in[((ici*10 + zi)*10 + yi)*XPAD + xi] = v;
        }
        for (int i = tid; i < SW2_N; i += 256)
            s_w[i] = g_w2r[ic0*27*C_IN + i];
        __syncthreads();

        #pragma unroll 1
        for (int ici = 0; ici < ICC; ici++) {
            #pragma unroll 1
            for (int dz = 0; dz < 3; dz++) {
                #pragma unroll
                for (int dy = 0; dy < 3; dy++) {
                    const float* base =
                        &s_in[((ici*10 + zz + dz)*10 + yy + dy)*XPAD + xg*8];
                    float4 ra = *(const float4*)(base);
                    float4 rb = *(const float4*)(base + 4);
                    float2 rc = *(const float2*)(base + 8);
                    float rr[10] = {ra.x,ra.y,ra.z,ra.w,
                                    rb.x,rb.y,rb.z,rb.w, rc.x,rc.y};
                    #pragma unroll
                    for (int dx = 0; dx < 3; dx++) {
                        const float4* wp = (const float4*)
                            &s_w[((ici*27 + (dz*3 + dy)*3 + dx) << 4) + og*8];
                        float4 w0 = wp[0], w1v = wp[1];
                        float wv[8] = {w0.x,w0.y,w0.z,w0.w,
                                       w1v.x,w1v.y,w1v.z,w1v.w};
                        #pragma unroll
                        for (int v = 0; v < 8; v++) {
                            float in = rr[dx + v];
                            #pragma unroll
                            for (int o = 0; o < 8; o++)
                                acc[v*8 + o] += in * wv[o];
                        }
                    }
                }
            }
        }
        __syncthreads();
    }

    // Euler-Maruyama update (in-place on y; pointwise -> safe)
    const float sn = 0.1f * 0.22360679774997896f;   // sigma * sqrt(dt)
    const int ox = x0 + xg*8, oy = y0 + yy, oz = z0 + zz;
    #pragma unroll
    for (int o = 0; o < 8; o++) {
        int oc  = og*8 + o;
        float b = b2[oc];
        int idx = oc*SSS + oz*SS + oy*S + ox;
        float4 y0v = *(const float4*)&yio[idx];
        float4 y1v = *(const float4*)&yio[idx + 4];
        float4 z0v = *(const float4*)&nz[idx];
        float4 z1v = *(const float4*)&nz[idx + 4];
        float4 o0, o1;
        o0.x = y0v.x + (acc[0*8+o] + b)*DT_F + sn*z0v.x;
        o0.y = y0v.y + (acc[1*8+o] + b)*DT_F + sn*z0v.y;
        o0.z = y0v.z + (acc[2*8+o] + b)*DT_F + sn*z0v.z;
        o0.w = y0v.w + (acc[3*8+o] + b)*DT_F + sn*z0v.w;
        o1.x = y1v.x + (acc[4*8+o] + b)*DT_F + sn*z1v.x;
        o1.y = y1v.y + (acc[5*8+o] + b)*DT_F + sn*z1v.y;
        o1.z = y1v.z + (acc[6*8+o] + b)*DT_F + sn*z1v.z;
        o1.w = y1v.w + (acc[7*8+o] + b)*DT_F + sn*z1v.w;
        *(float4*)&yio[idx]     = o0;
        *(float4*)&yio[idx + 4] = o1;
    }
}

// ---------------------------------------------------------------------------
// Launch: inputs = [x, integration_time, w1, b1, w2, b2, noise]
// ---------------------------------------------------------------------------
extern "C" void kernel_launch(void* const* d_in, const int* in_sizes, int n_in,
                              void* d_out, int out_size) {
    const float* x  = (const float*)d_in[0];
    const float* w1 = (const float*)d_in[2];
    const float* b1 = (const float*)d_in[3];
    const float* w2 = (const float*)d_in[4];
    const float* b2 = (const float*)d_in[5];
    const float* nz = (const float*)d_in[6];

    float *yp, *hp;
    cudaGetSymbolAddress((void**)&yp, g_y);
    cudaGetSymbolAddress((void**)&hp, g_h);

    const int smem1 = (SIN1_N + SW1_N) * (int)sizeof(float);  // 78336 B
    const int smem2 = (SIN2_N + SW2_N) * (int)sizeof(float);  // 77824 B
    cudaFuncSetAttribute(conv1_tanh_kernel,
                         cudaFuncAttributeMaxDynamicSharedMemorySize, smem1);
    cudaFuncSetAttribute(conv2_update_kernel,
                         cudaFuncAttributeMaxDynamicSharedMemorySize, smem2);

    cudaMemcpyAsync(yp, x, (size_t)NELEM * sizeof(float),
                    cudaMemcpyDeviceToDevice, 0);

    reorder_w_kernel<<<(C_IN*27*C_HID + 255)/256, 256>>>(w1, w2);

    dim3 grid1(S/16, S/4, S/4);   // (4,16,16) = 1024 blocks
    dim3 grid2(S/16, S/8, S/8);   // (4,8,8)   = 256 blocks
    for (int s = 0; s < NSTEPS; s++) {
        conv1_tanh_kernel<<<grid1, 256, smem1>>>(yp, hp, b1);
        conv2_update_kernel<<<grid2, 256, smem2>>>(hp, yp, b2,
                                                   nz + (size_t)s * NELEM);
    }

    cudaMemcpyAsync(d_out, yp, (size_t)NELEM * sizeof(float),
                    cudaMemcpyDeviceToDevice, 0);
}

// round 6
// speedup vs baseline: 1.2783x; 1.0711x over previous
#include <cuda_runtime.h>
#include <math.h>

// Problem constants
#define S     64
#define SS    (S*S)          // 4096
#define SSS   (S*S*S)        // 262144
#define C_IN  16
#define C_HID 64
#define NELEM (C_IN*SSS)     // 4194304
#define NSTEPS 20
#define DT_F   0.05f

#define ICC   8              // input-channel chunk
#define XPAD  20             // padded x-row (80B, 16B-aligned)

// conv1: tile 16x4x4
#define SIN1_N (ICC*6*6*XPAD)     // 5760 floats
#define SW1_N  (ICC*27*C_HID)     // 13824 floats
// conv2: tile 16x8x8
#define SIN2_N (ICC*10*10*XPAD)   // 16000 floats
#define SW2_N  (ICC*27*C_IN)      // 3456 floats

// Scratch (device globals: allocation-free rule)
__device__ float g_y[NELEM];
__device__ float g_h[C_HID*SSS];
__device__ float g_w1r[C_IN*27*C_HID];   // [ic][tap][oc]
__device__ float g_w2r[C_HID*27*C_IN];   // [ic][tap][oc]

// ---- packed f32x2 helpers ----
__device__ __forceinline__ unsigned long long dupf(float v) {
    unsigned long long r;
    asm("mov.b64 %0, {%1, %1};" : "=l"(r) : "f"(v));
    return r;
}
__device__ __forceinline__ void ffma2(unsigned long long& acc,
                                      unsigned long long a,
                                      unsigned long long b) {
    asm("fma.rn.f32x2 %0, %1, %2, %0;" : "+l"(acc) : "l"(a), "l"(b));
}
__device__ __forceinline__ float2 unpack2(unsigned long long v) {
    float2 f;
    asm("mov.b64 {%0, %1}, %2;" : "=f"(f.x), "=f"(f.y) : "l"(v));
    return f;
}

// ---------------------------------------------------------------------------
// Reorder weights: w[oc][ic][tap] -> wr[ic][tap][oc]
// ---------------------------------------------------------------------------
__global__ void reorder_w_kernel(const float* __restrict__ w1,
                                 const float* __restrict__ w2) {
    int i = blockIdx.x * blockDim.x + threadIdx.x;
    if (i >= C_IN*27*C_HID) return;
    {
        int oc = i & 63; int t = i >> 6; int tap = t % 27; int ic = t / 27;
        g_w1r[i] = w1[(oc*C_IN + ic)*27 + tap];
    }
    {
        int oc = i & 15; int t = i >> 4; int tap = t % 27; int ic = t / 27;
        g_w2r[i] = w2[(oc*C_HID + ic)*27 + tap];
    }
}

// ---------------------------------------------------------------------------
// Conv1 (16 -> 64) + tanh.  Tile 16x4x4.  256 threads:
//   og = tid>>5 (warp id) -> 8 oc (og*8..og*8+7); weight LDS is pure broadcast
//   vg = tid&31 -> 8 x-voxels: xg in {0,1}, yy 0..3, zz 0..3
// acc2[v*4+op]: 32 f32x2 pairs (oc even/odd), FFMA2 inner loop.
// ---------------------------------------------------------------------------
__global__ __launch_bounds__(256, 2)
void conv1_tanh_kernel(const float* __restrict__ yin,
                       float* __restrict__ hout,
                       const float* __restrict__ b1) {
    extern __shared__ float sm[];
    float* s_in = sm;               // [ICC][6][6][XPAD]
    float* s_w  = sm + SIN1_N;      // [ICC][27][64]

    const int tid = threadIdx.x;
    const int og  = tid >> 5;           // warp id: 8 oc-groups
    const int vg  = tid & 31;
    const int xg  = vg & 1;
    const int yy  = (vg >> 1) & 3;
    const int zz  = vg >> 3;
    const int x0  = blockIdx.x * 16;
    const int y0  = blockIdx.y * 4;
    const int z0  = blockIdx.z * 4;

    unsigned long long acc2[32];
    #pragma unroll
    for (int i = 0; i < 32; i++) acc2[i] = 0ull;

    for (int c = 0; c < C_IN/ICC; c++) {
        const int ic0 = c * ICC;
        for (int i = tid; i < ICC*6*6*18; i += 256) {
            int xi = i % 18; int r = i / 18;
            int yi = r % 6;  r /= 6;
            int zi = r % 6;  int ici = r / 6;
            int gx = x0 + xi - 1, gy = y0 + yi - 1, gz = z0 + zi - 1;
            float v = 0.f;
            if ((unsigned)gx < S && (unsigned)gy < S && (unsigned)gz < S)
                v = yin[(ic0 + ici)*SSS + gz*SS + gy*S + gx];
            s_in[((ici*6 + zi)*6 + yi)*XPAD + xi] = v;
        }
        for (int i = tid; i < SW1_N; i += 256)
            s_w[i] = g_w1r[ic0*27*C_HID + i];
        __syncthreads();

        #pragma unroll 1
        for (int ici = 0; ici < ICC; ici++) {
            #pragma unroll 1
            for (int dz = 0; dz < 3; dz++) {
                #pragma unroll
                for (int dy = 0; dy < 3; dy++) {
                    const float* base =
                        &s_in[((ici*6 + zz + dz)*6 + yy + dy)*XPAD + xg*8];
                    float4 ra = *(const float4*)(base);
                    float4 rb = *(const float4*)(base + 4);
                    float2 rc = *(const float2*)(base + 8);
                    float rr[10] = {ra.x,ra.y,ra.z,ra.w,
                                    rb.x,rb.y,rb.z,rb.w, rc.x,rc.y};
                    unsigned long long din[10];
                    #pragma unroll
                    for (int k = 0; k < 10; k++) din[k] = dupf(rr[k]);
                    #pragma unroll
                    for (int dx = 0; dx < 3; dx++) {
                        const ulonglong2* wp = (const ulonglong2*)
                            &s_w[((ici*27 + (dz*3 + dy)*3 + dx) << 6) + og*8];
                        ulonglong2 wa = wp[0];   // (w0,w1),(w2,w3)
                        ulonglong2 wb = wp[1];   // (w4,w5),(w6,w7)
                        #pragma unroll
                        for (int v = 0; v < 8; v++) {
                            unsigned long long in2 = din[dx + v];
                            ffma2(acc2[v*4 + 0], in2, wa.x);
                            ffma2(acc2[v*4 + 1], in2, wa.y);
                            ffma2(acc2[v*4 + 2], in2, wb.x);
                            ffma2(acc2[v*4 + 3], in2, wb.y);
                        }
                    }
                }
            }
        }
        __syncthreads();
    }

    // bias + tanh + vectorized store (8 oc x 8 voxels)
    const int ox = x0 + xg*8, oy = y0 + yy, oz = z0 + zz;
    #pragma unroll
    for (int op = 0; op < 4; op++) {
        int oce = og*8 + 2*op;
        float bl = b1[oce], bh = b1[oce + 1];
        float2 p[8];
        #pragma unroll
        for (int v = 0; v < 8; v++) p[v] = unpack2(acc2[v*4 + op]);
        float4 e0, e1, o0, o1;
        e0.x = tanhf(p[0].x + bl); e0.y = tanhf(p[1].x + bl);
        e0.z = tanhf(p[2].x + bl); e0.w = tanhf(p[3].x + bl);
        e1.x = tanhf(p[4].x + bl); e1.y = tanhf(p[5].x + bl);
        e1.z = tanhf(p[6].x + bl); e1.w = tanhf(p[7].x + bl);
        o0.x = tanhf(p[0].y + bh); o0.y = tanhf(p[1].y + bh);
        o0.z = tanhf(p[2].y + bh); o0.w = tanhf(p[3].y + bh);
        o1.x = tanhf(p[4].y + bh); o1.y = tanhf(p[5].y + bh);
        o1.z = tanhf(p[6].y + bh); o1.w = tanhf(p[7].y + bh);
        float* pe = &hout[oce*SSS + oz*SS + oy*S + ox];
        *(float4*)pe             = e0;
        *(float4*)(pe + 4)       = e1;
        *(float4*)(pe + SSS)     = o0;
        *(float4*)(pe + SSS + 4) = o1;
    }
}

// ---------------------------------------------------------------------------
// Conv2 (64 -> 16) + Euler update.  Tile 16x8x8.  256 threads:
//   og = tid>>7 (0/1) -> 8 oc; constant per warp -> weight broadcast
//   vg = tid&127 -> xg in {0,1}, yy 0..7, zz 0..7
// ---------------------------------------------------------------------------
__global__ __launch_bounds__(256, 2)
void conv2_update_kernel(const float* __restrict__ hin,
                         float* __restrict__ yio,
                         const float* __restrict__ b2,
                         const float* __restrict__ nz) {
    extern __shared__ float sm[];
    float* s_in = sm;               // [ICC][10][10][XPAD]
    float* s_w  = sm + SIN2_N;      // [ICC][27][16]

    const int tid = threadIdx.x;
    const int og  = tid >> 7;           // 0/1, constant within warp
    const int vg  = tid & 127;
    const int xg  = vg & 1;
    const int yy  = (vg >> 1) & 7;
    const int zz  = vg >> 4;
    const int x0  = blockIdx.x * 16;
    const int y0  = blockIdx.y * 8;
    const int z0  = blockIdx.z * 8;

    unsigned long long acc2[32];
    #pragma unroll
    for (int i = 0; i < 32; i++) acc2[i] = 0ull;

    for (int c = 0; c < C_HID/ICC; c++) {
        const int ic0 = c * ICC;
        for (int i = tid; i < ICC*10*10*18; i += 256) {
            int xi = i % 18; int r = i / 18;
            int yi = r % 10; r /= 10;
            int zi = r % 10; int ici = r / 10;
            int gx = x0 + xi - 1, gy = y0 + yi - 1, gz = z0 + zi - 1;
            float v = 0.f;
            if ((unsigned)gx < S && (unsigned)gy < S && (unsigned)gz < S)
                v = hin[(ic0 + ici)*SSS + gz*SS + gy*S + gx];
            s_in[((ici*10 + zi)*10 + yi)*XPAD + xi] = v;
        }
        for (int i = tid; i < SW2_N; i += 256)
            s_w[i] = g_w2r[ic0*27*C_IN + i];
        __syncthreads();

        #pragma unroll 1
        for (int ici = 0; ici < ICC; ici++) {
            #pragma unroll 1
            for (int dz = 0; dz < 3; dz++) {
                #pragma unroll
                for (int dy = 0; dy < 3; dy++) {
                    const float* base =
                        &s_in[((ici*10 + zz + dz)*10 + yy + dy)*XPAD + xg*8];
                    float4 ra = *(const float4*)(base);
                    float4 rb = *(const float4*)(base + 4);
                    float2 rc = *(const float2*)(base + 8);
                    float rr[10] = {ra.x,ra.y,ra.z,ra.w,
                                    rb.x,rb.y,rb.z,rb.w, rc.x,rc.y};
                    unsigned long long din[10];
                    #pragma unroll
                    for (int k = 0; k < 10; k++) din[k] = dupf(rr[k]);
                    #pragma unroll
                    for (int dx = 0; dx < 3; dx++) {
                        const ulonglong2* wp = (const ulonglong2*)
                            &s_w[((ici*27 + (dz*3 + dy)*3 + dx) << 4) + og*8];
                        ulonglong2 wa = wp[0];
                        ulonglong2 wb = wp[1];
                        #pragma unroll
                        for (int v = 0; v < 8; v++) {
                            unsigned long long in2 = din[dx + v];
                            ffma2(acc2[v*4 + 0], in2, wa.x);
                            ffma2(acc2[v*4 + 1], in2, wa.y);
                            ffma2(acc2[v*4 + 2], in2, wb.x);
                            ffma2(acc2[v*4 + 3], in2, wb.y);
                        }
                    }
                }
            }
        }
        __syncthreads();
    }

    // Euler-Maruyama update (in-place on y; pointwise -> safe)
    const float sn = 0.1f * 0.22360679774997896f;   // sigma * sqrt(dt)
    const int ox = x0 + xg*8, oy = y0 + yy, oz = z0 + zz;
    #pragma unroll
    for (int op = 0; op < 4; op++) {
        int oce = og*8 + 2*op;
        float bl = b2[oce], bh = b2[oce + 1];
        float2 p[8];
        #pragma unroll
        for (int v = 0; v < 8; v++) p[v] = unpack2(acc2[v*4 + op]);

        int ide = oce*SSS + oz*SS + oy*S + ox;
        int ido = ide + SSS;
        float4 ye0 = *(const float4*)&yio[ide];
        float4 ye1 = *(const float4*)&yio[ide + 4];
        float4 yo0 = *(const float4*)&yio[ido];
        float4 yo1 = *(const float4*)&yio[ido + 4];
        float4 ze0 = *(const float4*)&nz[ide];
        float4 ze1 = *(const float4*)&nz[ide + 4];
        float4 zo0 = *(const float4*)&nz[ido];
        float4 zo1 = *(const float4*)&nz[ido + 4];
        float4 r0, r1, r2, r3;
        r0.x = ye0.x + (p[0].x + bl)*DT_F + sn*ze0.x;
        r0.y = ye0.y + (p[1].x + bl)*DT_F + sn*ze0.y;
        r0.z = ye0.z + (p[2].x + bl)*DT_F + sn*ze0.z;
        r0.w = ye0.w + (p[3].x + bl)*DT_F + sn*ze0.w;
        r1.x = ye1.x + (p[4].x + bl)*DT_F + sn*ze1.x;
        r1.y = ye1.y + (p[5].x + bl)*DT_F + sn*ze1.y;
        r1.z = ye1.z + (p[6].x + bl)*DT_F + sn*ze1.z;
        r1.w = ye1.w + (p[7].x + bl)*DT_F + sn*ze1.w;
        r2.x = yo0.x + (p[0].y + bh)*DT_F + sn*zo0.x;
        r2.y = yo0.y + (p[1].y + bh)*DT_F + sn*zo0.y;
        r2.z = yo0.z + (p[2].y + bh)*DT_F + sn*zo0.z;
        r2.w = yo0.w + (p[3].y + bh)*DT_F + sn*zo0.w;
        r3.x = yo1.x + (p[4].y + bh)*DT_F + sn*zo1.x;
        r3.y = yo1.y + (p[5].y + bh)*DT_F + sn*zo1.y;
        r3.z = yo1.z + (p[6].y + bh)*DT_F + sn*zo1.z;
        r3.w = yo1.w + (p[7].y + bh)*DT_F + sn*zo1.w;
        *(float4*)&yio[ide]     = r0;
        *(float4*)&yio[ide + 4] = r1;
        *(float4*)&yio[ido]     = r2;
        *(float4*)&yio[ido + 4] = r3;
    }
}

// ---------------------------------------------------------------------------
// Launch: inputs = [x, integration_time, w1, b1, w2, b2, noise]
// ---------------------------------------------------------------------------
extern "C" void kernel_launch(void* const* d_in, const int* in_sizes, int n_in,
                              void* d_out, int out_size) {
    const float* x  = (const float*)d_in[0];
    const float* w1 = (const float*)d_in[2];
    const float* b1 = (const float*)d_in[3];
    const float* w2 = (const float*)d_in[4];
    const float* b2 = (const float*)d_in[5];
    const float* nz = (const float*)d_in[6];

    float *yp, *hp;
    cudaGetSymbolAddress((void**)&yp, g_y);
    cudaGetSymbolAddress((void**)&hp, g_h);

    const int smem1 = (SIN1_N + SW1_N) * (int)sizeof(float);  // 78336 B
    const int smem2 = (SIN2_N + SW2_N) * (int)sizeof(float);  // 77824 B
    cudaFuncSetAttribute(conv1_tanh_kernel,
                         cudaFuncAttributeMaxDynamicSharedMemorySize, smem1);
    cudaFuncSetAttribute(conv2_update_kernel,
                         cudaFuncAttributeMaxDynamicSharedMemorySize, smem2);

    cudaMemcpyAsync(yp, x, (size_t)NELEM * sizeof(float),
                    cudaMemcpyDeviceToDevice, 0);

    reorder_w_kernel<<<(C_IN*27*C_HID + 255)/256, 256>>>(w1, w2);

    dim3 grid1(S/16, S/4, S/4);   // (4,16,16) = 1024 blocks
    dim3 grid2(S/16, S/8, S/8);   // (4,8,8)   = 256 blocks
    for (int s = 0; s < NSTEPS; s++) {
        conv1_tanh_kernel<<<grid1, 256, smem1>>>(yp, hp, b1);
        conv2_update_kernel<<<grid2, 256, smem2>>>(hp, yp, b2,
                                                   nz + (size_t)s * NELEM);
    }

    cudaMemcpyAsync(d_out, yp, (size_t)NELEM * sizeof(float),
                    cudaMemcpyDeviceToDevice, 0);
}

// round 7
// speedup vs baseline: 1.4491x; 1.1336x over previous
#include <cuda_runtime.h>
#include <math.h>

// Problem constants
#define S     64
#define SS    (S*S)          // 4096
#define SSS   (S*S*S)        // 262144
#define C_IN  16
#define C_HID 64
#define NELEM (C_IN*SSS)     // 4194304
#define NSTEPS 20
#define DT_F   0.05f

#define ICC   4              // input-channel chunk (smaller -> deeper pipeline)
#define XPAD  20             // padded x-row (80B, 16B-aligned)

// conv1: tile 16x4x4, 4 chunks
#define NCH1   (C_IN/ICC)            // 4
#define SIN1C  (ICC*6*6*XPAD)        // 2880 floats
#define SW1C   (ICC*27*C_HID)        // 6912 floats
#define CH1    (SIN1C + SW1C)        // 9792 floats per buffer
// conv2: tile 16x8x8, 16 chunks
#define NCH2   (C_HID/ICC)           // 16
#define SIN2C  (ICC*10*10*XPAD)      // 8000 floats
#define SW2C   (ICC*27*C_IN)         // 1728 floats
#define CH2    (SIN2C + SW2C)        // 9728 floats per buffer

// Scratch (device globals: allocation-free rule)
__device__ float g_y[NELEM];
__device__ float g_h[C_HID*SSS];
__device__ float g_w1r[C_IN*27*C_HID];   // [ic][tap][oc]
__device__ float g_w2r[C_HID*27*C_IN];   // [ic][tap][oc]

// ---- packed f32x2 helpers ----
__device__ __forceinline__ unsigned long long dupf(float v) {
    unsigned long long r;
    asm("mov.b64 %0, {%1, %1};" : "=l"(r) : "f"(v));
    return r;
}
__device__ __forceinline__ void ffma2(unsigned long long& acc,
                                      unsigned long long a,
                                      unsigned long long b) {
    asm("fma.rn.f32x2 %0, %1, %2, %0;" : "+l"(acc) : "l"(a), "l"(b));
}
__device__ __forceinline__ float2 unpack2(unsigned long long v) {
    float2 f;
    asm("mov.b64 {%0, %1}, %2;" : "=f"(f.x), "=f"(f.y) : "l"(v));
    return f;
}

// ---- cp.async helpers ----
__device__ __forceinline__ void cp4(unsigned int dst, const void* src) {
    asm volatile("cp.async.ca.shared.global [%0], [%1], 4;"
                 :: "r"(dst), "l"(src));
}
__device__ __forceinline__ void cp16(unsigned int dst, const void* src) {
    asm volatile("cp.async.cg.shared.global [%0], [%1], 16;"
                 :: "r"(dst), "l"(src));
}
__device__ __forceinline__ void cp_commit() {
    asm volatile("cp.async.commit_group;");
}
template<int N> __device__ __forceinline__ void cp_wait() {
    asm volatile("cp.async.wait_group %0;" :: "n"(N));
}
__device__ __forceinline__ void sts1(unsigned int dst, float v) {
    asm volatile("st.shared.f32 [%0], %1;" :: "r"(dst), "f"(v));
}

// ---------------------------------------------------------------------------
// Reorder weights: w[oc][ic][tap] -> wr[ic][tap][oc]
// ---------------------------------------------------------------------------
__global__ void reorder_w_kernel(const float* __restrict__ w1,
                                 const float* __restrict__ w2) {
    int i = blockIdx.x * blockDim.x + threadIdx.x;
    if (i >= C_IN*27*C_HID) return;
    {
        int oc = i & 63; int t = i >> 6; int tap = t % 27; int ic = t / 27;
        g_w1r[i] = w1[(oc*C_IN + ic)*27 + tap];
    }
    {
        int oc = i & 15; int t = i >> 4; int tap = t % 27; int ic = t / 27;
        g_w2r[i] = w2[(oc*C_HID + ic)*27 + tap];
    }
}

// ---------------------------------------------------------------------------
// Chunk loaders (cp.async; caller commits the group)
// ---------------------------------------------------------------------------
// conv1 input: [ICC][6][6][18] halo tile from yin, chunk base channel ic0.
__device__ __forceinline__ void load_in1(unsigned int sb,
                                         const float* __restrict__ src,
                                         int ic0, int x0, int y0, int z0,
                                         int tid) {
    for (int i = tid; i < ICC*6*6*18; i += 256) {
        int xi = i % 18; int r = i / 18;
        int yi = r % 6;  int zi = (r / 6) % 6;  int ici = r / 36;
        int gx = x0 + xi - 1, gy = y0 + yi - 1, gz = z0 + zi - 1;
        unsigned int dst = sb + (unsigned)((((ici*6 + zi)*6 + yi)*XPAD + xi)*4);
        if ((unsigned)gx < S && (unsigned)gy < S && (unsigned)gz < S)
            cp4(dst, &src[(ic0 + ici)*SSS + gz*SS + gy*S + gx]);
        else
            sts1(dst, 0.f);
    }
}
// conv2 input: [ICC][10][10][18]
__device__ __forceinline__ void load_in2(unsigned int sb,
                                         const float* __restrict__ src,
                                         int ic0, int x0, int y0, int z0,
                                         int tid) {
    for (int i = tid; i < ICC*10*10*18; i += 256) {
        int xi = i % 18; int r = i / 18;
        int yi = r % 10; int zi = (r / 10) % 10;  int ici = r / 100;
        int gx = x0 + xi - 1, gy = y0 + yi - 1, gz = z0 + zi - 1;
        unsigned int dst = sb + (unsigned)((((ici*10 + zi)*10 + yi)*XPAD + xi)*4);
        if ((unsigned)gx < S && (unsigned)gy < S && (unsigned)gz < S)
            cp4(dst, &src[(ic0 + ici)*SSS + gz*SS + gy*S + gx]);
        else
            sts1(dst, 0.f);
    }
}
// contiguous aligned weight slice, n16 = count of 16B units
__device__ __forceinline__ void load_w(unsigned int sb,
                                       const float* __restrict__ src,
                                       int n16, int tid) {
    for (int i = tid; i < n16; i += 256)
        cp16(sb + (unsigned)(i*16), src + i*4);
}

// ---------------------------------------------------------------------------
// Conv1 (16 -> 64) + tanh.  Tile 16x4x4.  256 threads.  Pipelined chunks.
//   og = tid>>5 (warp) -> 8 oc; weight LDS is pure broadcast
//   vg = tid&31 -> 8 x-voxels: xg in {0,1}, yy 0..3, zz 0..3
// ---------------------------------------------------------------------------
__global__ __launch_bounds__(256, 2)
void conv1_tanh_kernel(const float* __restrict__ yin,
                       float* __restrict__ hout,
                       const float* __restrict__ b1) {
    extern __shared__ float sm[];

    const int tid = threadIdx.x;
    const int og  = tid >> 5;
    const int vg  = tid & 31;
    const int xg  = vg & 1;
    const int yy  = (vg >> 1) & 3;
    const int zz  = vg >> 3;
    const int x0  = blockIdx.x * 16;
    const int y0  = blockIdx.y * 4;
    const int z0  = blockIdx.z * 4;

    const unsigned int sb0 =
        (unsigned int)__cvta_generic_to_shared(sm);

    unsigned long long acc2[32];
    #pragma unroll
    for (int i = 0; i < 32; i++) acc2[i] = 0ull;

    // preload chunks 0,1
    #pragma unroll
    for (int p = 0; p < 2; p++) {
        unsigned int sb = sb0 + (unsigned)(p*CH1*4);
        load_in1(sb, yin, p*ICC, x0, y0, z0, tid);
        load_w(sb + SIN1C*4, g_w1r + p*ICC*27*C_HID, SW1C/4, tid);
        cp_commit();
    }

    for (int c = 0; c < NCH1; c++) {
        if (c < NCH1 - 1) cp_wait<1>(); else cp_wait<0>();
        __syncthreads();

        const float* s_in = sm + (c & 1)*CH1;
        const float* s_w  = s_in + SIN1C;

        #pragma unroll 1
        for (int ici = 0; ici < ICC; ici++) {
            #pragma unroll 1
            for (int dz = 0; dz < 3; dz++) {
                #pragma unroll
                for (int dy = 0; dy < 3; dy++) {
                    const float* base =
                        &s_in[((ici*6 + zz + dz)*6 + yy + dy)*XPAD + xg*8];
                    float4 ra = *(const float4*)(base);
                    float4 rb = *(const float4*)(base + 4);
                    float2 rc = *(const float2*)(base + 8);
                    float rr[10] = {ra.x,ra.y,ra.z,ra.w,
                                    rb.x,rb.y,rb.z,rb.w, rc.x,rc.y};
                    unsigned long long din[10];
                    #pragma unroll
                    for (int k = 0; k < 10; k++) din[k] = dupf(rr[k]);
                    #pragma unroll
                    for (int dx = 0; dx < 3; dx++) {
                        const ulonglong2* wp = (const ulonglong2*)
                            &s_w[((ici*27 + (dz*3 + dy)*3 + dx) << 6) + og*8];
                        ulonglong2 wa = wp[0];
                        ulonglong2 wb = wp[1];
                        #pragma unroll
                        for (int v = 0; v < 8; v++) {
                            unsigned long long in2 = din[dx + v];
                            ffma2(acc2[v*4 + 0], in2, wa.x);
                            ffma2(acc2[v*4 + 1], in2, wa.y);
                            ffma2(acc2[v*4 + 2], in2, wb.x);
                            ffma2(acc2[v*4 + 3], in2, wb.y);
                        }
                    }
                }
            }
        }
        __syncthreads();
        if (c + 2 < NCH1) {
            unsigned int sb = sb0 + (unsigned)((c & 1)*CH1*4);
            load_in1(sb, yin, (c + 2)*ICC, x0, y0, z0, tid);
            load_w(sb + SIN1C*4, g_w1r + (c + 2)*ICC*27*C_HID, SW1C/4, tid);
            cp_commit();
        }
    }

    // bias + tanh + vectorized store (8 oc x 8 voxels)
    const int ox = x0 + xg*8, oy = y0 + yy, oz = z0 + zz;
    #pragma unroll
    for (int op = 0; op < 4; op++) {
        int oce = og*8 + 2*op;
        float bl = b1[oce], bh = b1[oce + 1];
        float2 p[8];
        #pragma unroll
        for (int v = 0; v < 8; v++) p[v] = unpack2(acc2[v*4 + op]);
        float4 e0, e1, o0, o1;
        e0.x = tanhf(p[0].x + bl); e0.y = tanhf(p[1].x + bl);
        e0.z = tanhf(p[2].x + bl); e0.w = tanhf(p[3].x + bl);
        e1.x = tanhf(p[4].x + bl); e1.y = tanhf(p[5].x + bl);
        e1.z = tanhf(p[6].x + bl); e1.w = tanhf(p[7].x + bl);
        o0.x = tanhf(p[0].y + bh); o0.y = tanhf(p[1].y + bh);
        o0.z = tanhf(p[2].y + bh); o0.w = tanhf(p[3].y + bh);
        o1.x = tanhf(p[4].y + bh); o1.y = tanhf(p[5].y + bh);
        o1.z = tanhf(p[6].y + bh); o1.w = tanhf(p[7].y + bh);
        float* pe = &hout[oce*SSS + oz*SS + oy*S + ox];
        *(float4*)pe             = e0;
        *(float4*)(pe + 4)       = e1;
        *(float4*)(pe + SSS)     = o0;
        *(float4*)(pe + SSS + 4) = o1;
    }
}

// ---------------------------------------------------------------------------
// Conv2 (64 -> 16) + Euler update.  Tile 16x8x8.  256 threads.  Pipelined.
//   og = tid>>7 (0/1) -> 8 oc; constant per warp -> weight broadcast
//   vg = tid&127 -> xg in {0,1}, yy 0..7, zz 0..7
// ---------------------------------------------------------------------------
__global__ __launch_bounds__(256, 2)
void conv2_update_kernel(const float* __restrict__ hin,
                         float* __restrict__ yio,
                         const float* __restrict__ b2,
                         const float* __restrict__ nz) {
    extern __shared__ float sm[];

    const int tid = threadIdx.x;
    const int og  = tid >> 7;
    const int vg  = tid & 127;
    const int xg  = vg & 1;
    const int yy  = (vg >> 1) & 7;
    const int zz  = vg >> 4;
    const int x0  = blockIdx.x * 16;
    const int y0  = blockIdx.y * 8;
    const int z0  = blockIdx.z * 8;

    const unsigned int sb0 =
        (unsigned int)__cvta_generic_to_shared(sm);

    unsigned long long acc2[32];
    #pragma unroll
    for (int i = 0; i < 32; i++) acc2[i] = 0ull;

    #pragma unroll
    for (int p = 0; p < 2; p++) {
        unsigned int sb = sb0 + (unsigned)(p*CH2*4);
        load_in2(sb, hin, p*ICC, x0, y0, z0, tid);
        load_w(sb + SIN2C*4, g_w2r + p*ICC*27*C_IN, SW2C/4, tid);
        cp_commit();
    }

    for (int c = 0; c < NCH2; c++) {
        if (c < NCH2 - 1) cp_wait<1>(); else cp_wait<0>();
        __syncthreads();

        const float* s_in = sm + (c & 1)*CH2;
        const float* s_w  = s_in + SIN2C;

        #pragma unroll 1
        for (int ici = 0; ici < ICC; ici++) {
            #pragma unroll 1
            for (int dz = 0; dz < 3; dz++) {
                #pragma unroll
                for (int dy = 0; dy < 3; dy++) {
                    const float* base =
                        &s_in[((ici*10 + zz + dz)*10 + yy + dy)*XPAD + xg*8];
                    float4 ra = *(const float4*)(base);
                    float4 rb = *(const float4*)(base + 4);
                    float2 rc = *(const float2*)(base + 8);
                    float rr[10] = {ra.x,ra.y,ra.z,ra.w,
                                    rb.x,rb.y,rb.z,rb.w, rc.x,rc.y};
                    unsigned long long din[10];
                    #pragma unroll
                    for (int k = 0; k < 10; k++) din[k] = dupf(rr[k]);
                    #pragma unroll
                    for (int dx = 0; dx < 3; dx++) {
                        const ulonglong2* wp = (const ulonglong2*)
                            &s_w[((ici*27 + (dz*3 + dy)*3 + dx) << 4) + og*8];
                        ulonglong2 wa = wp[0];
                        ulonglong2 wb = wp[1];
                        #pragma unroll
                        for (int v = 0; v < 8; v++) {
                            unsigned long long in2 = din[dx + v];
                            ffma2(acc2[v*4 + 0], in2, wa.x);
                            ffma2(acc2[v*4 + 1], in2, wa.y);
                            ffma2(acc2[v*4 + 2], in2, wb.x);
                            ffma2(acc2[v*4 + 3], in2, wb.y);
                        }
                    }
                }
            }
        }
        __syncthreads();
        if (c + 2 < NCH2) {
            unsigned int sb = sb0 + (unsigned)((c & 1)*CH2*4);
            load_in2(sb, hin, (c + 2)*ICC, x0, y0, z0, tid);
            load_w(sb + SIN2C*4, g_w2r + (c + 2)*ICC*27*C_IN, SW2C/4, tid);
            cp_commit();
        }
    }

    // Euler-Maruyama update (in-place on y; pointwise -> safe)
    const float sn = 0.1f * 0.22360679774997896f;   // sigma * sqrt(dt)
    const int ox = x0 + xg*8, oy = y0 + yy, oz = z0 + zz;
    #pragma unroll
    for (int op = 0; op < 4; op++) {
        int oce = og*8 + 2*op;
        float bl = b2[oce], bh = b2[oce + 1];
        float2 p[8];
        #pragma unroll
        for (int v = 0; v < 8; v++) p[v] = unpack2(acc2[v*4 + op]);

        int ide = oce*SSS + oz*SS + oy*S + ox;
        int ido = ide + SSS;
        float4 ye0 = *(const float4*)&yio[ide];
        float4 ye1 = *(const float4*)&yio[ide + 4];
        float4 yo0 = *(const float4*)&yio[ido];
        float4 yo1 = *(const float4*)&yio[ido + 4];
        float4 ze0 = *(const float4*)&nz[ide];
        float4 ze1 = *(const float4*)&nz[ide + 4];
        float4 zo0 = *(const float4*)&nz[ido];
        float4 zo1 = *(const float4*)&nz[ido + 4];
        float4 r0, r1, r2, r3;
        r0.x = ye0.x + (p[0].x + bl)*DT_F + sn*ze0.x;
        r0.y = ye0.y + (p[1].x + bl)*DT_F + sn*ze0.y;
        r0.z = ye0.z + (p[2].x + bl)*DT_F + sn*ze0.z;
        r0.w = ye0.w + (p[3].x + bl)*DT_F + sn*ze0.w;
        r1.x = ye1.x + (p[4].x + bl)*DT_F + sn*ze1.x;
        r1.y = ye1.y + (p[5].x + bl)*DT_F + sn*ze1.y;
        r1.z = ye1.z + (p[6].x + bl)*DT_F + sn*ze1.z;
        r1.w = ye1.w + (p[7].x + bl)*DT_F + sn*ze1.w;
        r2.x = yo0.x + (p[0].y + bh)*DT_F + sn*zo0.x;
        r2.y = yo0.y + (p[1].y + bh)*DT_F + sn*zo0.y;
        r2.z = yo0.z + (p[2].y + bh)*DT_F + sn*zo0.z;
        r2.w = yo0.w + (p[3].y + bh)*DT_F + sn*zo0.w;
        r3.x = yo1.x + (p[4].y + bh)*DT_F + sn*zo1.x;
        r3.y = yo1.y + (p[5].y + bh)*DT_F + sn*zo1.y;
        r3.z = yo1.z + (p[6].y + bh)*DT_F + sn*zo1.z;
        r3.w = yo1.w + (p[7].y + bh)*DT_F + sn*zo1.w;
        *(float4*)&yio[ide]     = r0;
        *(float4*)&yio[ide + 4] = r1;
        *(float4*)&yio[ido]     = r2;
        *(float4*)&yio[ido + 4] = r3;
    }
}

// ---------------------------------------------------------------------------
// Launch: inputs = [x, integration_time, w1, b1, w2, b2, noise]
// ---------------------------------------------------------------------------
extern "C" void kernel_launch(void* const* d_in, const int* in_sizes, int n_in,
                              void* d_out, int out_size) {
    const float* x  = (const float*)d_in[0];
    const float* w1 = (const float*)d_in[2];
    const float* b1 = (const float*)d_in[3];
    const float* w2 = (const float*)d_in[4];
    const float* b2 = (const float*)d_in[5];
    const float* nz = (const float*)d_in[6];

    float *yp, *hp;
    cudaGetSymbolAddress((void**)&yp, g_y);
    cudaGetSymbolAddress((void**)&hp, g_h);

    const int smem1 = 2 * CH1 * (int)sizeof(float);  // 78336 B
    const int smem2 = 2 * CH2 * (int)sizeof(float);  // 77824 B
    cudaFuncSetAttribute(conv1_tanh_kernel,
                         cudaFuncAttributeMaxDynamicSharedMemorySize, smem1);
    cudaFuncSetAttribute(conv2_update_kernel,
                         cudaFuncAttributeMaxDynamicSharedMemorySize, smem2);

    cudaMemcpyAsync(yp, x, (size_t)NELEM * sizeof(float),
                    cudaMemcpyDeviceToDevice, 0);

    reorder_w_kernel<<<(C_IN*27*C_HID + 255)/256, 256>>>(w1, w2);

    dim3 grid1(S/16, S/4, S/4);   // (4,16,16) = 1024 blocks
    dim3 grid2(S/16, S/8, S/8);   // (4,8,8)   = 256 blocks
    for (int s = 0; s < NSTEPS; s++) {
        conv1_tanh_kernel<<<grid1, 256, smem1>>>(yp, hp, b1);
        conv2_update_kernel<<<grid2, 256, smem2>>>(hp, yp, b2,
                                                   nz + (size_t)s * NELEM);
    }

    cudaMemcpyAsync(d_out, yp, (size_t)NELEM * sizeof(float),
                    cudaMemcpyDeviceToDevice, 0);
}

// round 9
// speedup vs baseline: 1.4513x; 1.0016x over previous
#include <cuda_runtime.h>
#include <math.h>

// Problem constants
#define S     64
#define SS    (S*S)          // 4096
#define SSS   (S*S*S)        // 262144
#define C_IN  16
#define C_HID 64
#define NELEM (C_IN*SSS)     // 4194304
#define NSTEPS 20
#define DT_F   0.05f

#define ICC   4              // input-channel chunk (smaller -> deeper pipeline)
#define XPAD  20             // padded x-row (80B, 16B-aligned)

// conv1: tile 16x4x4, 4 chunks
#define NCH1   (C_IN/ICC)            // 4
#define SIN1C  (ICC*6*6*XPAD)        // 2880 floats
#define SW1C   (ICC*27*C_HID)        // 6912 floats
#define CH1    (SIN1C + SW1C)        // 9792 floats per buffer
// conv2: tile 16x8x8, 16 chunks
#define NCH2   (C_HID/ICC)           // 16
#define SIN2C  (ICC*10*10*XPAD)      // 8000 floats
#define SW2C   (ICC*27*C_IN)         // 1728 floats
#define CH2    (SIN2C + SW2C)        // 9728 floats per buffer

// Scratch (device globals: allocation-free rule)
__device__ float g_y[NELEM];
__device__ float g_h[C_HID*SSS];
__device__ float g_w1r[C_IN*27*C_HID];   // [ic][tap][oc]
__device__ float g_w2r[C_HID*27*C_IN];   // [ic][tap][oc]

// ---- packed f32x2 helpers ----
__device__ __forceinline__ unsigned long long dupf(float v) {
    unsigned long long r;
    asm("mov.b64 %0, {%1, %1};" : "=l"(r) : "f"(v));
    return r;
}
__device__ __forceinline__ void ffma2(unsigned long long& acc,
                                      unsigned long long a,
                                      unsigned long long b) {
    asm("fma.rn.f32x2 %0, %1, %2, %0;" : "+l"(acc) : "l"(a), "l"(b));
}
__device__ __forceinline__ float2 unpack2(unsigned long long v) {
    float2 f;
    asm("mov.b64 {%0, %1}, %2;" : "=f"(f.x), "=f"(f.y) : "l"(v));
    return f;
}

// ---- cp.async helpers ----
__device__ __forceinline__ void cp4(unsigned int dst, const void* src) {
    asm volatile("cp.async.ca.shared.global [%0], [%1], 4;"
                 :: "r"(dst), "l"(src));
}
__device__ __forceinline__ void cp16(unsigned int dst, const void* src) {
    asm volatile("cp.async.cg.shared.global [%0], [%1], 16;"
                 :: "r"(dst), "l"(src));
}
__device__ __forceinline__ void cp_commit() {
    asm volatile("cp.async.commit_group;");
}
template<int N> __device__ __forceinline__ void cp_wait() {
    asm volatile("cp.async.wait_group %0;" :: "n"(N));
}
__device__ __forceinline__ void sts1(unsigned int dst, float v) {
    asm volatile("st.shared.f32 [%0], %1;" :: "r"(dst), "f"(v));
}

// ---------------------------------------------------------------------------
// Reorder weights: w[oc][ic][tap] -> wr[ic][tap][oc]
// ---------------------------------------------------------------------------
__global__ void reorder_w_kernel(const float* __restrict__ w1,
                                 const float* __restrict__ w2) {
    int i = blockIdx.x * blockDim.x + threadIdx.x;
    if (i >= C_IN*27*C_HID) return;
    {
        int oc = i & 63; int t = i >> 6; int tap = t % 27; int ic = t / 27;
        g_w1r[i] = w1[(oc*C_IN + ic)*27 + tap];
    }
    {
        int oc = i & 15; int t = i >> 4; int tap = t % 27; int ic = t / 27;
        g_w2r[i] = w2[(oc*C_HID + ic)*27 + tap];
    }
}

// ---------------------------------------------------------------------------
// Chunk loaders (cp.async; caller commits the group)
// ---------------------------------------------------------------------------
// conv1 input: [ICC][6][6][18] halo tile from yin, chunk base channel ic0.
__device__ __forceinline__ void load_in1(unsigned int sb,
                                         const float* __restrict__ src,
                                         int ic0, int x0, int y0, int z0,
                                         int tid) {
    for (int i = tid; i < ICC*6*6*18; i += 256) {
        int xi = i % 18; int r = i / 18;
        int yi = r % 6;  int zi = (r / 6) % 6;  int ici = r / 36;
        int gx = x0 + xi - 1, gy = y0 + yi - 1, gz = z0 + zi - 1;
        unsigned int dst = sb + (unsigned)((((ici*6 + zi)*6 + yi)*XPAD + xi)*4);
        if ((unsigned)gx < S && (unsigned)gy < S && (unsigned)gz < S)
            cp4(dst, &src[(ic0 + ici)*SSS + gz*SS + gy*S + gx]);
        else
            sts1(dst, 0.f);
    }
}
// conv2 input: [ICC][10][10][18]
__device__ __forceinline__ void load_in2(unsigned int sb,
                                         const float* __restrict__ src,
                                         int ic0, int x0, int y0, int z0,
                                         int tid) {
    for (int i = tid; i < ICC*10*10*18; i += 256) {
        int xi = i % 18; int r = i / 18;
        int yi = r % 10; int zi = (r / 10) % 10;  int ici = r / 100;
        int gx = x0 + xi - 1, gy = y0 + yi - 1, gz = z0 + zi - 1;
        unsigned int dst = sb + (unsigned)((((ici*10 + zi)*10 + yi)*XPAD + xi)*4);
        if ((unsigned)gx < S && (unsigned)gy < S && (unsigned)gz < S)
            cp4(dst, &src[(ic0 + ici)*SSS + gz*SS + gy*S + gx]);
        else
            sts1(dst, 0.f);
    }
}
// contiguous aligned weight slice, n16 = count of 16B units
__device__ __forceinline__ void load_w(unsigned int sb,
                                       const float* __restrict__ src,
                                       int n16, int tid) {
    for (int i = tid; i < n16; i += 256)
        cp16(sb + (unsigned)(i*16), src + i*4);
}

// ---------------------------------------------------------------------------
// Conv1 (16 -> 64) + tanh.  Tile 16x4x4.  256 threads.  Pipelined chunks.
//   og = tid>>5 (warp) -> 8 oc; weight LDS is pure broadcast
//   vg = tid&31 -> 8 x-voxels: xg in {0,1}, yy 0..3, zz 0..3
// ---------------------------------------------------------------------------
__global__ __launch_bounds__(256, 2)
void conv1_tanh_kernel(const float* __restrict__ yin,
                       float* __restrict__ hout,
                       const float* __restrict__ b1) {
    extern __shared__ float sm[];

    const int tid = threadIdx.x;
    const int og  = tid >> 5;
    const int vg  = tid & 31;
    const int xg  = vg & 1;
    const int yy  = (vg >> 1) & 3;
    const int zz  = vg >> 3;
    const int x0  = blockIdx.x * 16;
    const int y0  = blockIdx.y * 4;
    const int z0  = blockIdx.z * 4;

    const unsigned int sb0 =
        (unsigned int)__cvta_generic_to_shared(sm);

    unsigned long long acc2[32];
    #pragma unroll
    for (int i = 0; i < 32; i++) acc2[i] = 0ull;

    // preload chunks 0,1
    #pragma unroll
    for (int p = 0; p < 2; p++) {
        unsigned int sb = sb0 + (unsigned)(p*CH1*4);
        load_in1(sb, yin, p*ICC, x0, y0, z0, tid);
        load_w(sb + SIN1C*4, g_w1r + p*ICC*27*C_HID, SW1C/4, tid);
        cp_commit();
    }

    for (int c = 0; c < NCH1; c++) {
        if (c < NCH1 - 1) cp_wait<1>(); else cp_wait<0>();
        __syncthreads();

        const float* s_in = sm + (c & 1)*CH1;
        const float* s_w  = s_in + SIN1C;

        #pragma unroll 1
        for (int ici = 0; ici < ICC; ici++) {
            #pragma unroll 1
            for (int dz = 0; dz < 3; dz++) {
                #pragma unroll
                for (int dy = 0; dy < 3; dy++) {
                    const float* base =
                        &s_in[((ici*6 + zz + dz)*6 + yy + dy)*XPAD + xg*8];
                    float4 ra = *(const float4*)(base);
                    float4 rb = *(const float4*)(base + 4);
                    float2 rc = *(const float2*)(base + 8);
                    float rr[10] = {ra.x,ra.y,ra.z,ra.w,
                                    rb.x,rb.y,rb.z,rb.w, rc.x,rc.y};
                    unsigned long long din[10];
                    #pragma unroll
                    for (int k = 0; k < 10; k++) din[k] = dupf(rr[k]);
                    #pragma unroll
                    for (int dx = 0; dx < 3; dx++) {
                        const ulonglong2* wp = (const ulonglong2*)
                            &s_w[((ici*27 + (dz*3 + dy)*3 + dx) << 6) + og*8];
                        ulonglong2 wa = wp[0];
                        ulonglong2 wb = wp[1];
                        #pragma unroll
                        for (int v = 0; v < 8; v++) {
                            unsigned long long in2 = din[dx + v];
                            ffma2(acc2[v*4 + 0], in2, wa.x);
                            ffma2(acc2[v*4 + 1], in2, wa.y);
                            ffma2(acc2[v*4 + 2], in2, wb.x);
                            ffma2(acc2[v*4 + 3], in2, wb.y);
                        }
                    }
                }
            }
        }
        __syncthreads();
        if (c + 2 < NCH1) {
            unsigned int sb = sb0 + (unsigned)((c & 1)*CH1*4);
            load_in1(sb, yin, (c + 2)*ICC, x0, y0, z0, tid);
            load_w(sb + SIN1C*4, g_w1r + (c + 2)*ICC*27*C_HID, SW1C/4, tid);
            cp_commit();
        }
    }

    // bias + tanh + vectorized store (8 oc x 8 voxels)
    const int ox = x0 + xg*8, oy = y0 + yy, oz = z0 + zz;
    #pragma unroll
    for (int op = 0; op < 4; op++) {
        int oce = og*8 + 2*op;
        float bl = b1[oce], bh = b1[oce + 1];
        float2 p[8];
        #pragma unroll
        for (int v = 0; v < 8; v++) p[v] = unpack2(acc2[v*4 + op]);
        float4 e0, e1, o0, o1;
        e0.x = tanhf(p[0].x + bl); e0.y = tanhf(p[1].x + bl);
        e0.z = tanhf(p[2].x + bl); e0.w = tanhf(p[3].x + bl);
        e1.x = tanhf(p[4].x + bl); e1.y = tanhf(p[5].x + bl);
        e1.z = tanhf(p[6].x + bl); e1.w = tanhf(p[7].x + bl);
        o0.x = tanhf(p[0].y + bh); o0.y = tanhf(p[1].y + bh);
        o0.z = tanhf(p[2].y + bh); o0.w = tanhf(p[3].y + bh);
        o1.x = tanhf(p[4].y + bh); o1.y = tanhf(p[5].y + bh);
        o1.z = tanhf(p[6].y + bh); o1.w = tanhf(p[7].y + bh);
        float* pe = &hout[oce*SSS + oz*SS + oy*S + ox];
        *(float4*)pe             = e0;
        *(float4*)(pe + 4)       = e1;
        *(float4*)(pe + SSS)     = o0;
        *(float4*)(pe + SSS + 4) = o1;
    }
}

// ---------------------------------------------------------------------------
// Conv2 (64 -> 16) + Euler update.  Tile 16x8x8.  256 threads.  Pipelined.
//   og = tid>>7 (0/1) -> 8 oc; constant per warp -> weight broadcast
//   vg = tid&127 -> xg in {0,1}, yy 0..7, zz 0..7
// ---------------------------------------------------------------------------
__global__ __launch_bounds__(256, 2)
void conv2_update_kernel(const float* __restrict__ hin,
                         float* __restrict__ yio,
                         const float* __restrict__ b2,
                         const float* __restrict__ nz) {
    extern __shared__ float sm[];

    const int tid = threadIdx.x;
    const int og  = tid >> 7;
    const int vg  = tid & 127;
    const int xg  = vg & 1;
    const int yy  = (vg >> 1) & 7;
    const int zz  = vg >> 4;
    const int x0  = blockIdx.x * 16;
    const int y0  = blockIdx.y * 8;
    const int z0  = blockIdx.z * 8;

    const unsigned int sb0 =
        (unsigned int)__cvta_generic_to_shared(sm);

    unsigned long long acc2[32];
    #pragma unroll
    for (int i = 0; i < 32; i++) acc2[i] = 0ull;

    #pragma unroll
    for (int p = 0; p < 2; p++) {
        unsigned int sb = sb0 + (unsigned)(p*CH2*4);
        load_in2(sb, hin, p*ICC, x0, y0, z0, tid);
        load_w(sb + SIN2C*4, g_w2r + p*ICC*27*C_IN, SW2C/4, tid);
        cp_commit();
    }

    for (int c = 0; c < NCH2; c++) {
        if (c < NCH2 - 1) cp_wait<1>(); else cp_wait<0>();
        __syncthreads();

        const float* s_in = sm + (c & 1)*CH2;
        const float* s_w  = s_in + SIN2C;

        #pragma unroll 1
        for (int ici = 0; ici < ICC; ici++) {
            #pragma unroll 1
            for (int dz = 0; dz < 3; dz++) {
                #pragma unroll
                for (int dy = 0; dy < 3; dy++) {
                    const float* base =
                        &s_in[((ici*10 + zz + dz)*10 + yy + dy)*XPAD + xg*8];
                    float4 ra = *(const float4*)(base);
                    float4 rb = *(const float4*)(base + 4);
                    float2 rc = *(const float2*)(base + 8);
                    float rr[10] = {ra.x,ra.y,ra.z,ra.w,
                                    rb.x,rb.y,rb.z,rb.w, rc.x,rc.y};
                    unsigned long long din[10];
                    #pragma unroll
                    for (int k = 0; k < 10; k++) din[k] = dupf(rr[k]);
                    #pragma unroll
                    for (int dx = 0; dx < 3; dx++) {
                        const ulonglong2* wp = (const ulonglong2*)
                            &s_w[((ici*27 + (dz*3 + dy)*3 + dx) << 4) + og*8];
                        ulonglong2 wa = wp[0];
                        ulonglong2 wb = wp[1];
                        #pragma unroll
                        for (int v = 0; v < 8; v++) {
                            unsigned long long in2 = din[dx + v];
                            ffma2(acc2[v*4 + 0], in2, wa.x);
                            ffma2(acc2[v*4 + 1], in2, wa.y);
                            ffma2(acc2[v*4 + 2], in2, wb.x);
                            ffma2(acc2[v*4 + 3], in2, wb.y);
                        }
                    }
                }
            }
        }
        __syncthreads();
        if (c + 2 < NCH2) {
            unsigned int sb = sb0 + (unsigned)((c & 1)*CH2*4);
            load_in2(sb, hin, (c + 2)*ICC, x0, y0, z0, tid);
            load_w(sb + SIN2C*4, g_w2r + (c + 2)*ICC*27*C_IN, SW2C/4, tid);
            cp_commit();
        }
    }

    // Euler-Maruyama update (in-place on y; pointwise -> safe)
    const float sn = 0.1f * 0.22360679774997896f;   // sigma * sqrt(dt)
    const int ox = x0 + xg*8, oy = y0 + yy, oz = z0 + zz;
    #pragma unroll
    for (int op = 0; op < 4; op++) {
        int oce = og*8 + 2*op;
        float bl = b2[oce], bh = b2[oce + 1];
        float2 p[8];
        #pragma unroll
        for (int v = 0; v < 8; v++) p[v] = unpack2(acc2[v*4 + op]);

        int ide = oce*SSS + oz*SS + oy*S + ox;
        int ido = ide + SSS;
        float4 ye0 = *(const float4*)&yio[ide];
        float4 ye1 = *(const float4*)&yio[ide + 4];
        float4 yo0 = *(const float4*)&yio[ido];
        float4 yo1 = *(const float4*)&yio[ido + 4];
        float4 ze0 = *(const float4*)&nz[ide];
        float4 ze1 = *(const float4*)&nz[ide + 4];
        float4 zo0 = *(const float4*)&nz[ido];
        float4 zo1 = *(const float4*)&nz[ido + 4];
        float4 r0, r1, r2, r3;
        r0.x = ye0.x + (p[0].x + bl)*DT_F + sn*ze0.x;
        r0.y = ye0.y + (p[1].x + bl)*DT_F + sn*ze0.y;
        r0.z = ye0.z + (p[2].x + bl)*DT_F + sn*ze0.z;
        r0.w = ye0.w + (p[3].x + bl)*DT_F + sn*ze0.w;
        r1.x = ye1.x + (p[4].x + bl)*DT_F + sn*ze1.x;
        r1.y = ye1.y + (p[5].x + bl)*DT_F + sn*ze1.y;
        r1.z = ye1.z + (p[6].x + bl)*DT_F + sn*ze1.z;
        r1.w = ye1.w + (p[7].x + bl)*DT_F + sn*ze1.w;
        r2.x = yo0.x + (p[0].y + bh)*DT_F + sn*zo0.x;
        r2.y = yo0.y + (p[1].y + bh)*DT_F + sn*zo0.y;
        r2.z = yo0.z + (p[2].y + bh)*DT_F + sn*zo0.z;
        r2.w = yo0.w + (p[3].y + bh)*DT_F + sn*zo0.w;
        r3.x = yo1.x + (p[4].y + bh)*DT_F + sn*zo1.x;
        r3.y = yo1.y + (p[5].y + bh)*DT_F + sn*zo1.y;
        r3.z = yo1.z + (p[6].y + bh)*DT_F + sn*zo1.z;
        r3.w = yo1.w + (p[7].y + bh)*DT_F + sn*zo1.w;
        *(float4*)&yio[ide]     = r0;
        *(float4*)&yio[ide + 4] = r1;
        *(float4*)&yio[ido]     = r2;
        *(float4*)&yio[ido + 4] = r3;
    }
}

// ---------------------------------------------------------------------------
// Launch: inputs = [x, integration_time, w1, b1, w2, b2, noise]
// ---------------------------------------------------------------------------
extern "C" void kernel_launch(void* const* d_in, const int* in_sizes, int n_in,
                              void* d_out, int out_size) {
    const float* x  = (const float*)d_in[0];
    const float* w1 = (const float*)d_in[2];
    const float* b1 = (const float*)d_in[3];
    const float* w2 = (const float*)d_in[4];
    const float* b2 = (const float*)d_in[5];
    const float* nz = (const float*)d_in[6];

    float *yp, *hp;
    cudaGetSymbolAddress((void**)&yp, g_y);
    cudaGetSymbolAddress((void**)&hp, g_h);

    const int smem1 = 2 * CH1 * (int)sizeof(float);  // 78336 B
    const int smem2 = 2 * CH2 * (int)sizeof(float);  // 77824 B
    cudaFuncSetAttribute(conv1_tanh_kernel,
                         cudaFuncAttributeMaxDynamicSharedMemorySize, smem1);
    cudaFuncSetAttribute(conv2_update_kernel,
                         cudaFuncAttributeMaxDynamicSharedMemorySize, smem2);

    cudaMemcpyAsync(yp, x, (size_t)NELEM * sizeof(float),
                    cudaMemcpyDeviceToDevice, 0);

    reorder_w_kernel<<<(C_IN*27*C_HID + 255)/256, 256>>>(w1, w2);

    dim3 grid1(S/16, S/4, S/4);   // (4,16,16) = 1024 blocks
    dim3 grid2(S/16, S/8, S/8);   // (4,8,8)   = 256 blocks
    for (int s = 0; s < NSTEPS; s++) {
        conv1_tanh_kernel<<<grid1, 256, smem1>>>(yp, hp, b1);
        conv2_update_kernel<<<grid2, 256, smem2>>>(hp, yp, b2,
                                                   nz + (size_t)s * NELEM);
    }

    cudaMemcpyAsync(d_out, yp, (size_t)NELEM * sizeof(float),
                    cudaMemcpyDeviceToDevice, 0);
}